// round 10
// baseline (speedup 1.0000x reference)
#include <cuda_runtime.h>

// RawISPProcessing: demosaic (2x bilinear; reference's flips cancel exactly) +
// fused channel-flip/awb/ccm 3x3 matrix (incl. the *2) + gamma, for pred & gt.
//
// R10: R9 packed-f32x2 dataflow, with the block-uniform fused matrix moved
// from 18 registers to shared memory (computed once per block). Cuts live
// regs ~80 -> ~62 to recover occupancy (31.7% -> ~50%).

#define HIN  512
#define WIN  512
#define PLANE (HIN * WIN)
#define OPLANE (1024 * 1024)
#define R_ROWS 4

typedef unsigned long long u64;

#define C025 0x3E8000003E800000ULL   // (0.25f, 0.25f)
#define C075 0x3F4000003F400000ULL   // (0.75f, 0.75f)
#define C05  0x3F0000003F000000ULL   // (0.5f,  0.5f)

__device__ __forceinline__ u64 pk(float lo, float hi) {
    u64 r; asm("mov.b64 %0, {%1, %2};" : "=l"(r) : "f"(lo), "f"(hi)); return r;
}
__device__ __forceinline__ void upk(u64 v, float& lo, float& hi) {
    asm("mov.b64 {%0, %1}, %2;" : "=f"(lo), "=f"(hi) : "l"(v));
}
__device__ __forceinline__ u64 fma2(u64 a, u64 b, u64 c) {
    u64 r; asm("fma.rn.f32x2 %0, %1, %2, %3;" : "=l"(r) : "l"(a), "l"(b), "l"(c)); return r;
}
__device__ __forceinline__ u64 mul2(u64 a, u64 b) {
    u64 r; asm("mul.rn.f32x2 %0, %1, %2;" : "=l"(r) : "l"(a), "l"(b)); return r;
}
__device__ __forceinline__ u64 add2(u64 a, u64 b) {
    u64 r; asm("add.rn.f32x2 %0, %1, %2;" : "=l"(r) : "l"(a), "l"(b)); return r;
}

// packed 0.25*a + 0.75*b
__device__ __forceinline__ u64 lerpE2(u64 a, u64 b) {
    return fma2(a, C025, mul2(b, C075));
}
// packed 0.75*a + 0.25*b
__device__ __forceinline__ u64 lerpO2(u64 a, u64 b) {
    return fma2(b, C025, mul2(a, C075));
}

__device__ __forceinline__ float gamma_pow(float v) {
    float l;
    asm("lg2.approx.f32 %0, %1;" : "=f"(l) : "f"(v));
    l *= 0.45454545454545453f;   // 1/2.2
    float r;
    asm("ex2.approx.f32 %0, %1;" : "=f"(r) : "f"(l));
    return r;
}

// Rolling state: packed h-lerps per plane, 2 pairs each.
// p[2k]   = plane k, output cols (0,1)
// p[2k+1] = plane k, output cols (2,3);  plane order: R, GR, GB, B
struct HL { u64 p[8]; };

__device__ __forceinline__ HL hlerp(const float* __restrict__ p,
                                    int wm, int w0, int wp2) {
    HL h;
#pragma unroll
    for (int k = 0; k < 4; k++) {
        const float* q = p + k * PLANE;
        float2 m = *(const float2*)(q + w0);   // (t1, t2), 8B aligned
        float t0 = q[wm], t3 = q[wp2];
        u64 A0 = pk(t0,  m.y);    // (t0, t2)
        u64 B0 = pk(m.x, m.x);    // (t1, t1)
        u64 A1 = pk(m.x, t3);     // (t1, t3)
        u64 B1 = pk(m.y, m.y);    // (t2, t2)
        h.p[2 * k]     = fma2(A0, C025, mul2(B0, C075));  // cols (0,1)
        h.p[2 * k + 1] = fma2(A1, C025, mul2(B1, C075));  // cols (2,3)
    }
    return h;
}

// packed matvec (coeffs from shared) + scalar gamma + streaming STG.128.
__device__ __forceinline__ void emit_row(float* __restrict__ po, const u64* sA,
                                         u64 rlo, u64 rhi, u64 glo, u64 ghi,
                                         u64 blo, u64 bhi) {
#pragma unroll
    for (int c = 0; c < 3; c++) {
        u64 ar = sA[c], ag = sA[3 + c], ab = sA[6 + c];   // LDS x3, reused lo+hi
        u64 olo = fma2(ar, rlo, fma2(ag, glo, mul2(ab, blo)));
        u64 ohi = fma2(ar, rhi, fma2(ag, ghi, mul2(ab, bhi)));
        float x, y, z, w;
        upk(olo, x, y);
        upk(ohi, z, w);
        float4 o = make_float4(gamma_pow(x), gamma_pow(y),
                               gamma_pow(z), gamma_pow(w));
        __stcs((float4*)(po + c * OPLANE), o);
    }
}

// Even output row: 0.25*ha + 0.75*hb.  G: even cols = avg(gr,gb), odd = gr.
__device__ __forceinline__ void emit_even(float* __restrict__ po, const u64* sA,
                                          const HL& ha, const HL& hb) {
    u64 rlo = lerpE2(ha.p[0], hb.p[0]), rhi = lerpE2(ha.p[1], hb.p[1]);
    u64 grlo = lerpE2(ha.p[2], hb.p[2]), grhi = lerpE2(ha.p[3], hb.p[3]);
    u64 gblo = lerpE2(ha.p[4], hb.p[4]), gbhi = lerpE2(ha.p[5], hb.p[5]);
    u64 blo = lerpE2(ha.p[6], hb.p[6]), bhi = lerpE2(ha.p[7], hb.p[7]);
    u64 avlo = mul2(add2(grlo, gblo), C05);
    u64 avhi = mul2(add2(grhi, gbhi), C05);
    float a0, a1, g0, g1, a2, a3, g2, g3;
    upk(avlo, a0, a1); upk(grlo, g0, g1);
    upk(avhi, a2, a3); upk(grhi, g2, g3);
    emit_row(po, sA, rlo, rhi, pk(a0, g1), pk(a2, g3), blo, bhi);
}

// Odd output row: 0.75*ha + 0.25*hb.  G: even cols = gb, odd = avg(gr,gb).
__device__ __forceinline__ void emit_odd(float* __restrict__ po, const u64* sA,
                                         const HL& ha, const HL& hb) {
    u64 rlo = lerpO2(ha.p[0], hb.p[0]), rhi = lerpO2(ha.p[1], hb.p[1]);
    u64 grlo = lerpO2(ha.p[2], hb.p[2]), grhi = lerpO2(ha.p[3], hb.p[3]);
    u64 gblo = lerpO2(ha.p[4], hb.p[4]), gbhi = lerpO2(ha.p[5], hb.p[5]);
    u64 blo = lerpO2(ha.p[6], hb.p[6]), bhi = lerpO2(ha.p[7], hb.p[7]);
    u64 avlo = mul2(add2(grlo, gblo), C05);
    u64 avhi = mul2(add2(grhi, gbhi), C05);
    float a0, a1, g0, g1, a2, a3, g2, g3;
    upk(avlo, a0, a1); upk(gblo, g0, g1);
    upk(avhi, a2, a3); upk(gbhi, g2, g3);
    emit_row(po, sA, rlo, rhi, pk(g0, a1), pk(g2, a3), blo, bhi);
}

__global__ __launch_bounds__(128)
void isp_kernel(const float* __restrict__ pred,
                const float* __restrict__ gt,
                const float* __restrict__ awb,
                const float* __restrict__ ccm,
                float* __restrict__ out) {
    __shared__ u64 sA[9];

    const int tid = threadIdx.y * 32 + threadIdx.x;
    const int cp = blockIdx.x * 32 + threadIdx.x;    // col-pair 0..255
    const int w0 = 2 * cp;                           // input col base
    const int strip = blockIdx.y * 4 + threadIdx.y;  // 0..127
    const int h0 = strip * R_ROWS;
    const int z = blockIdx.z;                        // which*8 + b
    const int b = z & 7;

    // fused matrix A[j*3+c] = 2 * sum_m awb[b,2-j,m] * ccm[b,m,2-c],
    // computed once per block into shared (block-uniform).
    if (tid < 9) {
        int j = tid / 3, c = tid % 3;
        const float* Aw = awb + b * 9;
        const float* Cm = ccm + b * 9;
        float s = 0.0f;
#pragma unroll
        for (int m = 0; m < 3; m++)
            s = fmaf(Aw[(2 - j) * 3 + m], Cm[m * 3 + (2 - c)], s);
        float v = 2.0f * s;
        sA[j * 3 + c] = pk(v, v);
    }

    const float* __restrict__ img =
        ((z >> 3) ? gt : pred) + (size_t)b * (4 * PLANE);

    const int wm  = max(w0 - 1, 0);
    const int wp2 = min(w0 + 2, WIN - 1);

    float* po = out + (size_t)z * (3 * (size_t)OPLANE)
                    + (size_t)(2 * h0) * 1024 + 4 * cp;

    const float* prow = img + h0 * WIN;
    HL ha = hlerp(img + max(h0 - 1, 0) * WIN, wm, w0, wp2);
    HL hb = hlerp(prow, wm, w0, wp2);

    __syncthreads();   // sA ready (overlapped with the two prologue hlerps)

    // first row of strip: output row 2*h0 (even) from (h0-1, h0)
    emit_even(po, sA, ha, hb);
    po += 1024;

#pragma unroll
    for (int r = 0; r < R_ROWS - 1; r++) {
        prow += WIN;
        ha = hb;
        hb = hlerp(prow, wm, w0, wp2);
        emit_odd(po, sA, ha, hb);          // row 2*(h0+r)+1
        emit_even(po + 1024, sA, ha, hb);  // row 2*(h0+r)+2
        po += 2048;
    }

    // last row of strip: output row 2*h0+2R-1 (odd) from (h0+R-1, h0+R)
    ha = hb;
    hb = hlerp(img + min(h0 + R_ROWS, HIN - 1) * WIN, wm, w0, wp2);
    emit_odd(po, sA, ha, hb);
}

extern "C" void kernel_launch(void* const* d_in, const int* in_sizes, int n_in,
                              void* d_out, int out_size) {
    const float* pred = (const float*)d_in[0];
    const float* gt   = (const float*)d_in[1];
    const float* awb  = (const float*)d_in[2];
    const float* ccm  = (const float*)d_in[3];
    // d_in[4] = rgb_gain: unused by the reference

    dim3 blk(32, 4);
    dim3 grd(8, 32, 16);   // 256 col-pairs x 128 strips x (2 images * 8 batches)
    isp_kernel<<<grd, blk>>>(pred, gt, awb, ccm, (float*)d_out);
}

// round 11
// speedup vs baseline: 1.0270x; 1.0270x over previous
#include <cuda_runtime.h>

// RawISPProcessing: demosaic (2x bilinear; reference's flips cancel exactly) +
// fused channel-flip/awb/ccm 3x3 matrix (incl. the *2) + gamma, for pred & gt.
//
// R11: R9 packed-f32x2 dataflow with a register diet:
//  - scalar A[9] (not packed 18 regs), packed per-use via asm VOLATILE mov.b64
//    (volatile defeats the LICM hoist that broke R10's shared-mem attempt)
//  - sub-form lerps: fma2(sub2(a,b), C025, b) — drops the C075 constant pair
//  - 64-thread blocks for finer wave packing (8192 blocks)

#define HIN  512
#define WIN  512
#define PLANE (HIN * WIN)
#define OPLANE (1024 * 1024)
#define R_ROWS 4

typedef unsigned long long u64;

#define C025 0x3E8000003E800000ULL   // (0.25f, 0.25f)
#define C05  0x3F0000003F000000ULL   // (0.5f,  0.5f)

__device__ __forceinline__ u64 pk(float lo, float hi) {
    u64 r; asm("mov.b64 %0, {%1, %2};" : "=l"(r) : "f"(lo), "f"(hi)); return r;
}
// volatile pack: not hoistable/CSE-able — keeps broadcast coeffs out of
// long-lived registers.
__device__ __forceinline__ u64 pkv(float v) {
    u64 r; asm volatile("mov.b64 %0, {%1, %1};" : "=l"(r) : "f"(v)); return r;
}
__device__ __forceinline__ void upk(u64 v, float& lo, float& hi) {
    asm("mov.b64 {%0, %1}, %2;" : "=f"(lo), "=f"(hi) : "l"(v));
}
__device__ __forceinline__ u64 fma2(u64 a, u64 b, u64 c) {
    u64 r; asm("fma.rn.f32x2 %0, %1, %2, %3;" : "=l"(r) : "l"(a), "l"(b), "l"(c)); return r;
}
__device__ __forceinline__ u64 mul2(u64 a, u64 b) {
    u64 r; asm("mul.rn.f32x2 %0, %1, %2;" : "=l"(r) : "l"(a), "l"(b)); return r;
}
__device__ __forceinline__ u64 sub2(u64 a, u64 b) {
    u64 r; asm("sub.rn.f32x2 %0, %1, %2;" : "=l"(r) : "l"(a), "l"(b)); return r;
}

// 0.25*a + 0.75*b  =  b + 0.25*(a-b)
__device__ __forceinline__ u64 lerpE2(u64 a, u64 b) {
    return fma2(sub2(a, b), C025, b);
}
// 0.75*a + 0.25*b  =  a + 0.25*(b-a)
__device__ __forceinline__ u64 lerpO2(u64 a, u64 b) {
    return fma2(sub2(b, a), C025, a);
}
// 0.5*(x+y) = y + 0.5*(x-y)
__device__ __forceinline__ u64 avg2(u64 x, u64 y) {
    return fma2(sub2(x, y), C05, y);
}

__device__ __forceinline__ float gamma_pow(float v) {
    float l;
    asm("lg2.approx.f32 %0, %1;" : "=f"(l) : "f"(v));
    l *= 0.45454545454545453f;   // 1/2.2
    float r;
    asm("ex2.approx.f32 %0, %1;" : "=f"(r) : "f"(l));
    return r;
}

// Rolling state: packed h-lerps per plane, 2 pairs each.
// p[2k] = plane k cols (0,1); p[2k+1] = plane k cols (2,3). Planes: R,GR,GB,B.
struct HL { u64 p[8]; };

__device__ __forceinline__ HL hlerp(const float* __restrict__ p,
                                    int wm, int w0, int wp2) {
    HL h;
#pragma unroll
    for (int k = 0; k < 4; k++) {
        const float* q = p + k * PLANE;
        float2 m = *(const float2*)(q + w0);   // (t1, t2), 8B aligned
        float t0 = q[wm], t3 = q[wp2];
        u64 A0 = pk(t0,  m.y);    // (t0, t2)
        u64 B0 = pk(m.x, m.x);    // (t1, t1)
        u64 A1 = pk(m.x, t3);     // (t1, t3)
        u64 B1 = pk(m.y, m.y);    // (t2, t2)
        h.p[2 * k]     = fma2(sub2(A0, B0), C025, B0);  // cols (0,1)
        h.p[2 * k + 1] = fma2(sub2(A1, B1), C025, B1);  // cols (2,3)
    }
    return h;
}

// packed matvec (scalar coeffs packed per-use, volatile) + gamma + STG.128.
__device__ __forceinline__ void emit_row(float* __restrict__ po, const float* A,
                                         u64 rlo, u64 rhi, u64 glo, u64 ghi,
                                         u64 blo, u64 bhi) {
#pragma unroll
    for (int c = 0; c < 3; c++) {
        u64 ar = pkv(A[c]), ag = pkv(A[3 + c]), ab = pkv(A[6 + c]);
        u64 olo = fma2(ar, rlo, fma2(ag, glo, mul2(ab, blo)));
        u64 ohi = fma2(ar, rhi, fma2(ag, ghi, mul2(ab, bhi)));
        float x, y, z, w;
        upk(olo, x, y);
        upk(ohi, z, w);
        float4 o = make_float4(gamma_pow(x), gamma_pow(y),
                               gamma_pow(z), gamma_pow(w));
        __stcs((float4*)(po + c * OPLANE), o);
    }
}

// Even output row: 0.25*ha + 0.75*hb.  G: even cols = avg(gr,gb), odd = gr.
__device__ __forceinline__ void emit_even(float* __restrict__ po, const float* A,
                                          const HL& ha, const HL& hb) {
    u64 rlo = lerpE2(ha.p[0], hb.p[0]), rhi = lerpE2(ha.p[1], hb.p[1]);
    u64 grlo = lerpE2(ha.p[2], hb.p[2]), grhi = lerpE2(ha.p[3], hb.p[3]);
    u64 gblo = lerpE2(ha.p[4], hb.p[4]), gbhi = lerpE2(ha.p[5], hb.p[5]);
    u64 blo = lerpE2(ha.p[6], hb.p[6]), bhi = lerpE2(ha.p[7], hb.p[7]);
    u64 avlo = avg2(grlo, gblo);
    u64 avhi = avg2(grhi, gbhi);
    float a0, a1, g0, g1, a2, a3, g2, g3;
    upk(avlo, a0, a1); upk(grlo, g0, g1);
    upk(avhi, a2, a3); upk(grhi, g2, g3);
    emit_row(po, A, rlo, rhi, pk(a0, g1), pk(a2, g3), blo, bhi);
}

// Odd output row: 0.75*ha + 0.25*hb.  G: even cols = gb, odd = avg(gr,gb).
__device__ __forceinline__ void emit_odd(float* __restrict__ po, const float* A,
                                         const HL& ha, const HL& hb) {
    u64 rlo = lerpO2(ha.p[0], hb.p[0]), rhi = lerpO2(ha.p[1], hb.p[1]);
    u64 grlo = lerpO2(ha.p[2], hb.p[2]), grhi = lerpO2(ha.p[3], hb.p[3]);
    u64 gblo = lerpO2(ha.p[4], hb.p[4]), gbhi = lerpO2(ha.p[5], hb.p[5]);
    u64 blo = lerpO2(ha.p[6], hb.p[6]), bhi = lerpO2(ha.p[7], hb.p[7]);
    u64 avlo = avg2(grlo, gblo);
    u64 avhi = avg2(grhi, gbhi);
    float a0, a1, g0, g1, a2, a3, g2, g3;
    upk(avlo, a0, a1); upk(gblo, g0, g1);
    upk(avhi, a2, a3); upk(gbhi, g2, g3);
    emit_row(po, A, rlo, rhi, pk(g0, a1), pk(g2, a3), blo, bhi);
}

__global__ __launch_bounds__(64)
void isp_kernel(const float* __restrict__ pred,
                const float* __restrict__ gt,
                const float* __restrict__ awb,
                const float* __restrict__ ccm,
                float* __restrict__ out) {
    const int cp = blockIdx.x * 32 + threadIdx.x;    // col-pair 0..255
    const int w0 = 2 * cp;                           // input col base
    const int strip = blockIdx.y * 2 + threadIdx.y;  // 0..127
    const int h0 = strip * R_ROWS;
    const int z = blockIdx.z;                        // which*8 + b
    const int b = z & 7;

    const float* __restrict__ img =
        ((z >> 3) ? gt : pred) + (size_t)b * (4 * PLANE);

    // fused matrix A[j*3+c] = 2 * sum_m awb[b,2-j,m] * ccm[b,m,2-c] (scalar, 9 regs)
    float A[9];
    {
        const float* Aw = awb + b * 9;
        const float* Cm = ccm + b * 9;
#pragma unroll
        for (int j = 0; j < 3; j++)
#pragma unroll
            for (int c = 0; c < 3; c++) {
                float s = 0.0f;
#pragma unroll
                for (int m = 0; m < 3; m++)
                    s = fmaf(__ldg(Aw + (2 - j) * 3 + m),
                             __ldg(Cm + m * 3 + (2 - c)), s);
                A[j * 3 + c] = 2.0f * s;
            }
    }

    const int wm  = max(w0 - 1, 0);
    const int wp2 = min(w0 + 2, WIN - 1);

    float* po = out + (size_t)z * (3 * (size_t)OPLANE)
                    + (size_t)(2 * h0) * 1024 + 4 * cp;

    const float* prow = img + h0 * WIN;
    HL ha = hlerp(img + max(h0 - 1, 0) * WIN, wm, w0, wp2);
    HL hb = hlerp(prow, wm, w0, wp2);

    // first row of strip: output row 2*h0 (even) from (h0-1, h0)
    emit_even(po, A, ha, hb);
    po += 1024;

#pragma unroll
    for (int r = 0; r < R_ROWS - 1; r++) {
        prow += WIN;
        ha = hb;
        hb = hlerp(prow, wm, w0, wp2);
        emit_odd(po, A, ha, hb);          // row 2*(h0+r)+1
        emit_even(po + 1024, A, ha, hb);  // row 2*(h0+r)+2
        po += 2048;
    }

    // last row of strip: output row 2*h0+2R-1 (odd) from (h0+R-1, h0+R)
    ha = hb;
    hb = hlerp(img + min(h0 + R_ROWS, HIN - 1) * WIN, wm, w0, wp2);
    emit_odd(po, A, ha, hb);
}

extern "C" void kernel_launch(void* const* d_in, const int* in_sizes, int n_in,
                              void* d_out, int out_size) {
    const float* pred = (const float*)d_in[0];
    const float* gt   = (const float*)d_in[1];
    const float* awb  = (const float*)d_in[2];
    const float* ccm  = (const float*)d_in[3];
    // d_in[4] = rgb_gain: unused by the reference

    dim3 blk(32, 2);
    dim3 grd(8, 64, 16);   // 256 col-pairs x 128 strips x (2 images * 8 batches)
    isp_kernel<<<grd, blk>>>(pred, gt, awb, ccm, (float*)d_out);
}